// round 2
// baseline (speedup 1.0000x reference)
#include <cuda_runtime.h>
#include <cstdint>

#define N_NODES 8192
#define F_DIM 128
#define ALPHA 0.3f
#define MAXDEG 512

// ---- device scratch (no allocations allowed) ----
__device__ float g_v[4 * F_DIM];                   // v1[h0],v1[h1],v2[h0],v2[h1]
__device__ float g_Sx[F_DIM];                      // column sums of x
__device__ float g_sa1[2 * N_NODES];               // [h][n]
__device__ float g_sa2[2 * N_NODES];               // [h][n]
__device__ float g_G[(size_t)N_NODES * 256];       // per-row [g_h0(128) | g_h1(128)]

// ============================================================
// Kernel 1: v1[h] = Wmap[h] @ a1_w[h], v2[h] = Wmap[h] @ a2_w[h]; zero Sx
// ============================================================
__global__ void prep_kernel(const float* __restrict__ Wmap,
                            const float* __restrict__ a1w,
                            const float* __restrict__ a2w) {
    int t = threadIdx.x;          // 0..255 -> (h,f)
    int h = t >> 7, f = t & 127;
    const float* wrow = Wmap + (size_t)(h * F_DIM + f) * 128;
    float s1 = 0.f, s2 = 0.f;
    for (int d = 0; d < 128; ++d) {
        float w = wrow[d];
        s1 = fmaf(w, a1w[h * 128 + d], s1);
        s2 = fmaf(w, a2w[h * 128 + d], s2);
    }
    g_v[h * F_DIM + f] = s1;
    g_v[2 * F_DIM + h * F_DIM + f] = s2;
    if (t < F_DIM) g_Sx[t] = 0.f;
}

// ============================================================
// Kernel 2: per-node scores sa1/sa2 + fused column sums of x
// ============================================================
__global__ void __launch_bounds__(256) score_kernel(const float* __restrict__ x,
                                                    const float* __restrict__ a1b,
                                                    const float* __restrict__ a2b) {
    __shared__ float sv[4 * 128];
    __shared__ float s_colp[8][128];
    int tid = threadIdx.x;               // 256
    sv[tid] = g_v[tid];
    sv[256 + tid] = g_v[256 + tid];

    int warp = tid >> 5, lane = tid & 31;
    int n = blockIdx.x * 8 + warp;
    const float* xr = x + (size_t)n * F_DIM;
    float x0 = xr[lane], x1 = xr[lane + 32], x2 = xr[lane + 64], x3 = xr[lane + 96];

    // stash for column-sum reduction
    s_colp[warp][lane]      = x0;
    s_colp[warp][lane + 32] = x1;
    s_colp[warp][lane + 64] = x2;
    s_colp[warp][lane + 96] = x3;
    __syncthreads();

    float s[4];
    #pragma unroll
    for (int q = 0; q < 4; ++q) {
        const float* v = sv + q * 128;
        float acc = x0 * v[lane] + x1 * v[lane + 32] + x2 * v[lane + 64] + x3 * v[lane + 96];
        #pragma unroll
        for (int o = 16; o > 0; o >>= 1)
            acc += __shfl_down_sync(0xffffffffu, acc, o);
        s[q] = acc;
    }
    if (lane == 0) {
        g_sa1[n]           = s[0] + a1b[0];
        g_sa1[N_NODES + n] = s[1] + a1b[1];
        g_sa2[n]           = s[2] + a2b[0];
        g_sa2[N_NODES + n] = s[3] + a2b[1];
    }

    // fused column sums: threads 0..127 reduce 8 rows, one atomic each
    if (tid < 128) {
        float cs = 0.f;
        #pragma unroll
        for (int w = 0; w < 8; ++w) cs += s_colp[w][tid];
        atomicAdd(&g_Sx[tid], cs);
    }
}

// ============================================================
// Kernel 3 (main): per-row adj scan -> sparse softmax -> weighted x gather
//   g_h[i,:] = c_ih*Sx + sum_{j in nbr(i)} beta_ijh * x[j,:]
// ============================================================
__global__ void __launch_bounds__(256) gat_main(const float* __restrict__ adj,
                                                const float* __restrict__ x) {
    __shared__ int   s_list[MAXDEG];
    __shared__ float s_w0[MAXDEG], s_w1[MAXDEG];
    __shared__ float s_g0[128], s_g1[128];
    __shared__ int   s_cnt;
    __shared__ float s_red[16];
    __shared__ float s_bc[4];

    int tid = threadIdx.x;
    int i = blockIdx.x;
    if (tid == 0) s_cnt = 0;
    if (tid < 128) { s_g0[tid] = 0.f; s_g1[tid] = 0.f; }
    __syncthreads();

    // ---- phase 1: streaming scan, front-batched loads (MLP=8), fast zero path ----
    const uint4* arow = reinterpret_cast<const uint4*>(adj + (size_t)i * N_NODES);
    uint4 a[8];
    #pragma unroll
    for (int it = 0; it < 8; ++it)
        a[it] = __ldcs(&arow[it * 256 + tid]);     // evict-first: don't pollute L2
    #pragma unroll
    for (int it = 0; it < 8; ++it) {
        uint4 v = a[it];
        if ((v.x | v.y | v.z | v.w) != 0u) {       // rare (~4% of quads)
            int jb = (it * 256 + tid) << 2;
            if (v.x) { int p = atomicAdd(&s_cnt, 1); if (p < MAXDEG) s_list[p] = jb; }
            if (v.y) { int p = atomicAdd(&s_cnt, 1); if (p < MAXDEG) s_list[p] = jb + 1; }
            if (v.z) { int p = atomicAdd(&s_cnt, 1); if (p < MAXDEG) s_list[p] = jb + 2; }
            if (v.w) { int p = atomicAdd(&s_cnt, 1); if (p < MAXDEG) s_list[p] = jb + 3; }
        }
    }
    __syncthreads();
    int deg = min(s_cnt, MAXDEG);

    float sa1_0 = g_sa1[i];
    float sa1_1 = g_sa1[N_NODES + i];

    // ---- phase 2: leaky scores + max (0 included for non-neighbors) ----
    float m0 = 0.f, m1 = 0.f;
    for (int t = tid; t < deg; t += 256) {
        int j = s_list[t];
        float w0 = sa1_0 + g_sa2[j];
        float w1 = sa1_1 + g_sa2[N_NODES + j];
        w0 = (w0 >= 0.f) ? w0 : ALPHA * w0;
        w1 = (w1 >= 0.f) ? w1 : ALPHA * w1;
        s_w0[t] = w0; s_w1[t] = w1;
        m0 = fmaxf(m0, w0); m1 = fmaxf(m1, w1);
    }
    #pragma unroll
    for (int o = 16; o > 0; o >>= 1) {
        m0 = fmaxf(m0, __shfl_down_sync(0xffffffffu, m0, o));
        m1 = fmaxf(m1, __shfl_down_sync(0xffffffffu, m1, o));
    }
    if ((tid & 31) == 0) { s_red[tid >> 5] = m0; s_red[8 + (tid >> 5)] = m1; }
    __syncthreads();
    if (tid == 0) {
        float p = 0.f, q = 0.f;
        for (int w = 0; w < 8; ++w) { p = fmaxf(p, s_red[w]); q = fmaxf(q, s_red[8 + w]); }
        s_bc[0] = p; s_bc[1] = q;
    }
    __syncthreads();
    m0 = s_bc[0]; m1 = s_bc[1];
    float em0 = __expf(-m0), em1 = __expf(-m1);

    // ---- phase 3: exp + sum -> Z ----
    float z0 = 0.f, z1 = 0.f;
    for (int t = tid; t < deg; t += 256) {
        float e0 = __expf(s_w0[t] - m0);
        float e1 = __expf(s_w1[t] - m1);
        s_w0[t] = e0; s_w1[t] = e1;
        z0 += e0; z1 += e1;
    }
    #pragma unroll
    for (int o = 16; o > 0; o >>= 1) {
        z0 += __shfl_down_sync(0xffffffffu, z0, o);
        z1 += __shfl_down_sync(0xffffffffu, z1, o);
    }
    if ((tid & 31) == 0) { s_red[tid >> 5] = z0; s_red[8 + (tid >> 5)] = z1; }
    __syncthreads();
    if (tid == 0) {
        float p = 0.f, q = 0.f;
        for (int w = 0; w < 8; ++w) { p += s_red[w]; q += s_red[8 + w]; }
        p += (float)(N_NODES - deg) * em0;
        q += (float)(N_NODES - deg) * em1;
        s_bc[2] = p; s_bc[3] = q;
    }
    __syncthreads();
    float iz0 = 1.f / s_bc[2];
    float iz1 = 1.f / s_bc[3];

    // ---- phase 4: exp -> beta = (e - exp(-m))/Z ----
    for (int t = tid; t < deg; t += 256) {
        s_w0[t] = (s_w0[t] - em0) * iz0;
        s_w1[t] = (s_w1[t] - em1) * iz1;
    }
    __syncthreads();

    // ---- phase 5: vectorized gather of x rows (8 slots x 32 lanes, float4) ----
    int lane = tid & 31;
    int slot = tid >> 5;
    const float4* x4 = reinterpret_cast<const float4*>(x);
    float g0a = 0.f, g0b = 0.f, g0c = 0.f, g0d = 0.f;
    float g1a = 0.f, g1b = 0.f, g1c = 0.f, g1d = 0.f;
    #pragma unroll 2
    for (int t = slot; t < deg; t += 8) {
        int j = s_list[t];
        float4 xv = __ldg(&x4[(size_t)j * 32 + lane]);
        float b0 = s_w0[t], b1 = s_w1[t];
        g0a = fmaf(b0, xv.x, g0a); g1a = fmaf(b1, xv.x, g1a);
        g0b = fmaf(b0, xv.y, g0b); g1b = fmaf(b1, xv.y, g1b);
        g0c = fmaf(b0, xv.z, g0c); g1c = fmaf(b1, xv.z, g1c);
        g0d = fmaf(b0, xv.w, g0d); g1d = fmaf(b1, xv.w, g1d);
    }
    int d4 = lane * 4;
    atomicAdd(&s_g0[d4 + 0], g0a); atomicAdd(&s_g0[d4 + 1], g0b);
    atomicAdd(&s_g0[d4 + 2], g0c); atomicAdd(&s_g0[d4 + 3], g0d);
    atomicAdd(&s_g1[d4 + 0], g1a); atomicAdd(&s_g1[d4 + 1], g1b);
    atomicAdd(&s_g1[d4 + 2], g1c); atomicAdd(&s_g1[d4 + 3], g1d);
    __syncthreads();

    if (tid < 128) {
        float sx = g_Sx[tid];
        float v0 = fmaf(em0 * iz0, sx, s_g0[tid]);
        float v1 = fmaf(em1 * iz1, sx, s_g1[tid]);
        g_G[(size_t)i * 256 + tid]       = v0;
        g_G[(size_t)i * 256 + 128 + tid] = v1;
    }
}

// ============================================================
// Kernel 4: out = 0.5*(G @ Kflat + bias0 + bias1) via tf32 MMA,
// 3-pass error compensation (hi*hi + hi*lo + lo*hi).
//   G: [8192,256]  Kflat: [256,128]
// CTA: 64 rows x 128 cols; warp tile 32x32 (2 m16 x 4 n8 subtiles)
// ============================================================
__device__ __forceinline__ uint32_t f2tf32(float x) {
    uint32_t r;
    asm("cvt.rna.tf32.f32 %0, %1;" : "=r"(r) : "f"(x));
    return r;
}

__device__ __forceinline__ void mma_tf32(float* d, const uint32_t* a, const uint32_t* b) {
    asm volatile(
        "mma.sync.aligned.m16n8k8.row.col.f32.tf32.tf32.f32 "
        "{%0,%1,%2,%3},{%4,%5,%6,%7},{%8,%9},{%0,%1,%2,%3};\n"
        : "+f"(d[0]), "+f"(d[1]), "+f"(d[2]), "+f"(d[3])
        : "r"(a[0]), "r"(a[1]), "r"(a[2]), "r"(a[3]), "r"(b[0]), "r"(b[1]));
}

__global__ void __launch_bounds__(256) gemm_tf32(const float* __restrict__ Kw,
                                                 const float* __restrict__ bias,
                                                 float* __restrict__ out) {
    int tid = threadIdx.x;
    int wid = tid >> 5, lane = tid & 31;
    int wm = wid & 1;           // 2 m-groups of 32 rows
    int wn = wid >> 1;          // 4 n-groups of 32 cols
    int grp = lane >> 2, thr = lane & 3;
    int rbase = blockIdx.x * 64 + wm * 32;
    int cbase = wn * 32;

    float acc[2][4][4];
    #pragma unroll
    for (int mi = 0; mi < 2; ++mi)
        #pragma unroll
        for (int ni = 0; ni < 4; ++ni)
            #pragma unroll
            for (int q = 0; q < 4; ++q) acc[mi][ni][q] = 0.f;

    #pragma unroll 1
    for (int kt = 0; kt < 32; ++kt) {
        int kb = kt * 8;
        // A fragments: rows rbase+mi*16+grp(+8), cols kb+thr(+4)
        uint32_t ah[2][4], al[2][4];
        #pragma unroll
        for (int mi = 0; mi < 2; ++mi) {
            const float* Ar = g_G + (size_t)(rbase + mi * 16 + grp) * 256 + kb + thr;
            float f0 = Ar[0];
            float f1 = Ar[8 * 256];
            float f2 = Ar[4];
            float f3 = Ar[8 * 256 + 4];
            ah[mi][0] = f2tf32(f0); al[mi][0] = f2tf32(f0 - __uint_as_float(ah[mi][0]));
            ah[mi][1] = f2tf32(f1); al[mi][1] = f2tf32(f1 - __uint_as_float(ah[mi][1]));
            ah[mi][2] = f2tf32(f2); al[mi][2] = f2tf32(f2 - __uint_as_float(ah[mi][2]));
            ah[mi][3] = f2tf32(f3); al[mi][3] = f2tf32(f3 - __uint_as_float(ah[mi][3]));
        }
        // B fragments: k rows kb+thr(+4), cols cbase+ni*8+grp
        uint32_t bh[4][2], bl[4][2];
        #pragma unroll
        for (int ni = 0; ni < 4; ++ni) {
            const float* Br = Kw + (size_t)(kb + thr) * 128 + cbase + ni * 8 + grp;
            float f0 = Br[0];
            float f1 = Br[4 * 128];
            bh[ni][0] = f2tf32(f0); bl[ni][0] = f2tf32(f0 - __uint_as_float(bh[ni][0]));
            bh[ni][1] = f2tf32(f1); bl[ni][1] = f2tf32(f1 - __uint_as_float(bh[ni][1]));
        }
        #pragma unroll
        for (int mi = 0; mi < 2; ++mi)
            #pragma unroll
            for (int ni = 0; ni < 4; ++ni) {
                mma_tf32(acc[mi][ni], ah[mi], bh[ni]);
                mma_tf32(acc[mi][ni], ah[mi], bl[ni]);
                mma_tf32(acc[mi][ni], al[mi], bh[ni]);
            }
    }

    // epilogue: out = 0.5*(acc + bias_h0 + bias_h1); pairs (c, c+1) -> float2
    #pragma unroll
    for (int mi = 0; mi < 2; ++mi) {
        #pragma unroll
        for (int ni = 0; ni < 4; ++ni) {
            int c0 = cbase + ni * 8 + 2 * thr;
            #pragma unroll
            for (int half = 0; half < 2; ++half) {
                int r = rbase + mi * 16 + grp + half * 8;
                size_t o = (size_t)r * 128 + c0;
                const float2 b0 = *reinterpret_cast<const float2*>(bias + o);
                const float2 b1 = *reinterpret_cast<const float2*>(bias + (size_t)N_NODES * 128 + o);
                float2 res;
                res.x = 0.5f * (acc[mi][ni][half * 2 + 0] + b0.x + b1.x);
                res.y = 0.5f * (acc[mi][ni][half * 2 + 1] + b0.y + b1.y);
                *reinterpret_cast<float2*>(out + o) = res;
            }
        }
    }
}

// ============================================================
extern "C" void kernel_launch(void* const* d_in, const int* in_sizes, int n_in,
                              void* d_out, int out_size) {
    const float* x    = (const float*)d_in[0];
    const float* adj  = (const float*)d_in[1];
    const float* Wmap = (const float*)d_in[2];
    const float* a1w  = (const float*)d_in[3];
    const float* a1b  = (const float*)d_in[4];
    const float* a2w  = (const float*)d_in[5];
    const float* a2b  = (const float*)d_in[6];
    const float* kern = (const float*)d_in[7];
    const float* bias = (const float*)d_in[8];
    float* out = (float*)d_out;

    prep_kernel<<<1, 256>>>(Wmap, a1w, a2w);
    score_kernel<<<1024, 256>>>(x, a1b, a2b);
    gat_main<<<N_NODES, 256>>>(adj, x);
    gemm_tf32<<<128, 256>>>(kern, bias, out);
}

// round 3
// speedup vs baseline: 1.2650x; 1.2650x over previous
#include <cuda_runtime.h>
#include <cstdint>

#define N_NODES 8192
#define F_DIM 128
#define ALPHA 0.3f
#define MAXDEG 512

// ---- device scratch (no allocations allowed) ----
__device__ float g_v[4 * F_DIM];                   // v1[h0],v1[h1],v2[h0],v2[h1]
__device__ float g_Sx[F_DIM];                      // column sums of x
__device__ float g_sa1[2 * N_NODES];               // [h][n]
__device__ float g_sa2[2 * N_NODES];               // [h][n]
__device__ float g_G[(size_t)N_NODES * 256];       // per-row [g_h0(128) | g_h1(128)]

// ============================================================
// Kernel 1: v1[h] = Wmap[h] @ a1_w[h], v2[h] = Wmap[h] @ a2_w[h]; zero Sx
// ============================================================
__global__ void prep_kernel(const float* __restrict__ Wmap,
                            const float* __restrict__ a1w,
                            const float* __restrict__ a2w) {
    int t = threadIdx.x;          // 0..255 -> (h,f)
    int h = t >> 7, f = t & 127;
    const float* wrow = Wmap + (size_t)(h * F_DIM + f) * 128;
    float s1 = 0.f, s2 = 0.f;
    for (int d = 0; d < 128; ++d) {
        float w = wrow[d];
        s1 = fmaf(w, a1w[h * 128 + d], s1);
        s2 = fmaf(w, a2w[h * 128 + d], s2);
    }
    g_v[h * F_DIM + f] = s1;
    g_v[2 * F_DIM + h * F_DIM + f] = s2;
    if (t < F_DIM) g_Sx[t] = 0.f;
}

// ============================================================
// Kernel 2: per-node scores sa1/sa2 + fused column sums of x
// ============================================================
__global__ void __launch_bounds__(256) score_kernel(const float* __restrict__ x,
                                                    const float* __restrict__ a1b,
                                                    const float* __restrict__ a2b) {
    __shared__ float sv[4 * 128];
    __shared__ float s_colp[8][128];
    int tid = threadIdx.x;               // 256
    sv[tid] = g_v[tid];
    sv[256 + tid] = g_v[256 + tid];

    int warp = tid >> 5, lane = tid & 31;
    int n = blockIdx.x * 8 + warp;
    const float* xr = x + (size_t)n * F_DIM;
    float x0 = xr[lane], x1 = xr[lane + 32], x2 = xr[lane + 64], x3 = xr[lane + 96];

    s_colp[warp][lane]      = x0;
    s_colp[warp][lane + 32] = x1;
    s_colp[warp][lane + 64] = x2;
    s_colp[warp][lane + 96] = x3;
    __syncthreads();

    float s[4];
    #pragma unroll
    for (int q = 0; q < 4; ++q) {
        const float* v = sv + q * 128;
        float acc = x0 * v[lane] + x1 * v[lane + 32] + x2 * v[lane + 64] + x3 * v[lane + 96];
        #pragma unroll
        for (int o = 16; o > 0; o >>= 1)
            acc += __shfl_down_sync(0xffffffffu, acc, o);
        s[q] = acc;
    }
    if (lane == 0) {
        g_sa1[n]           = s[0] + a1b[0];
        g_sa1[N_NODES + n] = s[1] + a1b[1];
        g_sa2[n]           = s[2] + a2b[0];
        g_sa2[N_NODES + n] = s[3] + a2b[1];
    }

    if (tid < 128) {
        float cs = 0.f;
        #pragma unroll
        for (int w = 0; w < 8; ++w) cs += s_colp[w][tid];
        atomicAdd(&g_Sx[tid], cs);
    }
}

// ============================================================
// Kernel 3 (main): per-row adj scan -> sparse softmax -> weighted x gather
// ============================================================
__global__ void __launch_bounds__(256) gat_main(const float* __restrict__ adj,
                                                const float* __restrict__ x) {
    __shared__ int   s_list[MAXDEG];
    __shared__ float s_w0[MAXDEG], s_w1[MAXDEG];
    __shared__ float s_p0[8][132], s_p1[8][132];   // per-slot gather partials
    __shared__ int   s_cnt;
    __shared__ float s_red[16];
    __shared__ float s_bc[4];

    int tid = threadIdx.x;
    int i = blockIdx.x;
    if (tid == 0) s_cnt = 0;
    __syncthreads();

    // ---- phase 1: streaming scan, 2 batches of 4 (MLP_p1=4), fast zero path ----
    const uint4* arow = reinterpret_cast<const uint4*>(adj + (size_t)i * N_NODES);
    #pragma unroll
    for (int half = 0; half < 2; ++half) {
        uint4 a[4];
        #pragma unroll
        for (int it = 0; it < 4; ++it)
            a[it] = __ldcs(&arow[(half * 4 + it) * 256 + tid]);
        #pragma unroll
        for (int it = 0; it < 4; ++it) {
            uint4 v = a[it];
            if ((v.x | v.y | v.z | v.w) != 0u) {
                int jb = ((half * 4 + it) * 256 + tid) << 2;
                if (v.x) { int p = atomicAdd(&s_cnt, 1); if (p < MAXDEG) s_list[p] = jb; }
                if (v.y) { int p = atomicAdd(&s_cnt, 1); if (p < MAXDEG) s_list[p] = jb + 1; }
                if (v.z) { int p = atomicAdd(&s_cnt, 1); if (p < MAXDEG) s_list[p] = jb + 2; }
                if (v.w) { int p = atomicAdd(&s_cnt, 1); if (p < MAXDEG) s_list[p] = jb + 3; }
            }
        }
    }
    __syncthreads();
    int deg = min(s_cnt, MAXDEG);

    float sa1_0 = g_sa1[i];
    float sa1_1 = g_sa1[N_NODES + i];

    // ---- phase 2: leaky scores + max (0 included for non-neighbors) ----
    float m0 = 0.f, m1 = 0.f;
    for (int t = tid; t < deg; t += 256) {
        int j = s_list[t];
        float w0 = sa1_0 + g_sa2[j];
        float w1 = sa1_1 + g_sa2[N_NODES + j];
        w0 = (w0 >= 0.f) ? w0 : ALPHA * w0;
        w1 = (w1 >= 0.f) ? w1 : ALPHA * w1;
        s_w0[t] = w0; s_w1[t] = w1;
        m0 = fmaxf(m0, w0); m1 = fmaxf(m1, w1);
    }
    #pragma unroll
    for (int o = 16; o > 0; o >>= 1) {
        m0 = fmaxf(m0, __shfl_down_sync(0xffffffffu, m0, o));
        m1 = fmaxf(m1, __shfl_down_sync(0xffffffffu, m1, o));
    }
    if ((tid & 31) == 0) { s_red[tid >> 5] = m0; s_red[8 + (tid >> 5)] = m1; }
    __syncthreads();
    if (tid == 0) {
        float p = 0.f, q = 0.f;
        for (int w = 0; w < 8; ++w) { p = fmaxf(p, s_red[w]); q = fmaxf(q, s_red[8 + w]); }
        s_bc[0] = p; s_bc[1] = q;
    }
    __syncthreads();
    m0 = s_bc[0]; m1 = s_bc[1];
    float em0 = __expf(-m0), em1 = __expf(-m1);

    // ---- phase 3: exp + sum -> Z ----
    float z0 = 0.f, z1 = 0.f;
    for (int t = tid; t < deg; t += 256) {
        float e0 = __expf(s_w0[t] - m0);
        float e1 = __expf(s_w1[t] - m1);
        s_w0[t] = e0; s_w1[t] = e1;
        z0 += e0; z1 += e1;
    }
    #pragma unroll
    for (int o = 16; o > 0; o >>= 1) {
        z0 += __shfl_down_sync(0xffffffffu, z0, o);
        z1 += __shfl_down_sync(0xffffffffu, z1, o);
    }
    if ((tid & 31) == 0) { s_red[tid >> 5] = z0; s_red[8 + (tid >> 5)] = z1; }
    __syncthreads();
    if (tid == 0) {
        float p = 0.f, q = 0.f;
        for (int w = 0; w < 8; ++w) { p += s_red[w]; q += s_red[8 + w]; }
        p += (float)(N_NODES - deg) * em0;
        q += (float)(N_NODES - deg) * em1;
        s_bc[2] = p; s_bc[3] = q;
    }
    __syncthreads();
    float iz0 = 1.f / s_bc[2];
    float iz1 = 1.f / s_bc[3];

    // ---- phase 4: vectorized gather (8 slots x 32 lanes, float4); beta folded in ----
    int lane = tid & 31;
    int slot = tid >> 5;
    const float4* x4 = reinterpret_cast<const float4*>(x);
    float g0a = 0.f, g0b = 0.f, g0c = 0.f, g0d = 0.f;
    float g1a = 0.f, g1b = 0.f, g1c = 0.f, g1d = 0.f;
    #pragma unroll 2
    for (int t = slot; t < deg; t += 8) {
        int j = s_list[t];
        float4 xv = __ldg(&x4[(size_t)j * 32 + lane]);
        float b0 = (s_w0[t] - em0) * iz0;
        float b1 = (s_w1[t] - em1) * iz1;
        g0a = fmaf(b0, xv.x, g0a); g1a = fmaf(b1, xv.x, g1a);
        g0b = fmaf(b0, xv.y, g0b); g1b = fmaf(b1, xv.y, g1b);
        g0c = fmaf(b0, xv.z, g0c); g1c = fmaf(b1, xv.z, g1c);
        g0d = fmaf(b0, xv.w, g0d); g1d = fmaf(b1, xv.w, g1d);
    }
    // per-slot partials via STS.128, then 8-way tree sum (no shared atomics)
    *reinterpret_cast<float4*>(&s_p0[slot][lane * 4]) = make_float4(g0a, g0b, g0c, g0d);
    *reinterpret_cast<float4*>(&s_p1[slot][lane * 4]) = make_float4(g1a, g1b, g1c, g1d);
    __syncthreads();

    if (tid < 128) {
        float v0 = 0.f, v1 = 0.f;
        #pragma unroll
        for (int s = 0; s < 8; ++s) { v0 += s_p0[s][tid]; v1 += s_p1[s][tid]; }
        float sx = g_Sx[tid];
        v0 = fmaf(em0 * iz0, sx, v0);
        v1 = fmaf(em1 * iz1, sx, v1);
        g_G[(size_t)i * 256 + tid]       = v0;
        g_G[(size_t)i * 256 + 128 + tid] = v1;
    }
}

// ============================================================
// Kernel 4: out = 0.5*(G @ Kflat + bias0 + bias1) via tf32 MMA,
// smem double-buffered. BM=32, BN=128, BK=32, grid=256, 128 thr (4 warps).
// ============================================================
__device__ __forceinline__ uint32_t f2tf32(float x) {
    uint32_t r;
    asm("cvt.rna.tf32.f32 %0, %1;" : "=r"(r) : "f"(x));
    return r;
}
__device__ __forceinline__ void mma_tf32(float* d, const uint32_t* a, const uint32_t* b) {
    asm volatile(
        "mma.sync.aligned.m16n8k8.row.col.f32.tf32.tf32.f32 "
        "{%0,%1,%2,%3},{%4,%5,%6,%7},{%8,%9},{%0,%1,%2,%3};\n"
        : "+f"(d[0]), "+f"(d[1]), "+f"(d[2]), "+f"(d[3])
        : "r"(a[0]), "r"(a[1]), "r"(a[2]), "r"(a[3]), "r"(b[0]), "r"(b[1]));
}

__global__ void __launch_bounds__(128) gemm_tf32(const float* __restrict__ Kw,
                                                 const float* __restrict__ bias,
                                                 float* __restrict__ out) {
    __shared__ float As[2][32][40];    // [buf][k][m], pad 40 -> frag bank = 8*thr+grp
    __shared__ float Bs[2][32][132];   // [buf][k][col]

    int tid = threadIdx.x;
    int wid = tid >> 5, lane = tid & 31;
    int grp = lane >> 2, thr = lane & 3;
    int row0 = blockIdx.x * 32;
    int cbase = wid * 32;

    // LDG staging indices
    int am = tid >> 3;                 // 0..15 (and +16)
    int akq = (tid & 7) * 4;           // k quad base
    int bk0 = tid >> 5;                // 0..3
    int bc4 = (tid & 31) * 4;          // col quad

    float4 ra[2], rb[8];

    auto ldg_chunk = [&](int c) {
        int kb = c * 32;
        ra[0] = *reinterpret_cast<const float4*>(g_G + (size_t)(row0 + am) * 256 + kb + akq);
        ra[1] = *reinterpret_cast<const float4*>(g_G + (size_t)(row0 + am + 16) * 256 + kb + akq);
        #pragma unroll
        for (int q = 0; q < 8; ++q)
            rb[q] = *reinterpret_cast<const float4*>(Kw + (size_t)(kb + bk0 + 4 * q) * 128 + bc4);
    };
    auto sts_chunk = [&](int buf) {
        As[buf][akq + 0][am] = ra[0].x; As[buf][akq + 1][am] = ra[0].y;
        As[buf][akq + 2][am] = ra[0].z; As[buf][akq + 3][am] = ra[0].w;
        As[buf][akq + 0][am + 16] = ra[1].x; As[buf][akq + 1][am + 16] = ra[1].y;
        As[buf][akq + 2][am + 16] = ra[1].z; As[buf][akq + 3][am + 16] = ra[1].w;
        #pragma unroll
        for (int q = 0; q < 8; ++q)
            *reinterpret_cast<float4*>(&Bs[buf][bk0 + 4 * q][bc4]) = rb[q];
    };

    float acc[2][4][4];
    #pragma unroll
    for (int mi = 0; mi < 2; ++mi)
        #pragma unroll
        for (int ni = 0; ni < 4; ++ni)
            #pragma unroll
            for (int q = 0; q < 4; ++q) acc[mi][ni][q] = 0.f;

    ldg_chunk(0);
    sts_chunk(0);
    __syncthreads();

    #pragma unroll 1
    for (int c = 0; c < 8; ++c) {
        int cur = c & 1;
        if (c < 7) ldg_chunk(c + 1);

        #pragma unroll
        for (int k8 = 0; k8 < 4; ++k8) {
            int kb = k8 * 8;
            uint32_t ah[2][4], al[2][4];
            #pragma unroll
            for (int mi = 0; mi < 2; ++mi) {
                float f0 = As[cur][kb + thr][mi * 16 + grp];
                float f1 = As[cur][kb + thr][mi * 16 + grp + 8];
                float f2 = As[cur][kb + thr + 4][mi * 16 + grp];
                float f3 = As[cur][kb + thr + 4][mi * 16 + grp + 8];
                ah[mi][0] = f2tf32(f0); al[mi][0] = f2tf32(f0 - __uint_as_float(ah[mi][0]));
                ah[mi][1] = f2tf32(f1); al[mi][1] = f2tf32(f1 - __uint_as_float(ah[mi][1]));
                ah[mi][2] = f2tf32(f2); al[mi][2] = f2tf32(f2 - __uint_as_float(ah[mi][2]));
                ah[mi][3] = f2tf32(f3); al[mi][3] = f2tf32(f3 - __uint_as_float(ah[mi][3]));
            }
            uint32_t bh[4][2], bl[4][2];
            #pragma unroll
            for (int ni = 0; ni < 4; ++ni) {
                float f0 = Bs[cur][kb + thr][cbase + ni * 8 + grp];
                float f1 = Bs[cur][kb + thr + 4][cbase + ni * 8 + grp];
                bh[ni][0] = f2tf32(f0); bl[ni][0] = f2tf32(f0 - __uint_as_float(bh[ni][0]));
                bh[ni][1] = f2tf32(f1); bl[ni][1] = f2tf32(f1 - __uint_as_float(bh[ni][1]));
            }
            #pragma unroll
            for (int mi = 0; mi < 2; ++mi)
                #pragma unroll
                for (int ni = 0; ni < 4; ++ni) {
                    mma_tf32(acc[mi][ni], ah[mi], bh[ni]);
                    mma_tf32(acc[mi][ni], ah[mi], bl[ni]);
                    mma_tf32(acc[mi][ni], al[mi], bh[ni]);
                }
        }

        if (c < 7) {
            sts_chunk(cur ^ 1);
            __syncthreads();
        }
    }

    // epilogue: out = 0.5*(acc + bias_h0 + bias_h1)
    #pragma unroll
    for (int mi = 0; mi < 2; ++mi) {
        #pragma unroll
        for (int ni = 0; ni < 4; ++ni) {
            int c0 = cbase + ni * 8 + 2 * thr;
            #pragma unroll
            for (int half = 0; half < 2; ++half) {
                int r = row0 + mi * 16 + grp + half * 8;
                size_t o = (size_t)r * 128 + c0;
                const float2 b0 = *reinterpret_cast<const float2*>(bias + o);
                const float2 b1 = *reinterpret_cast<const float2*>(bias + (size_t)N_NODES * 128 + o);
                float2 res;
                res.x = 0.5f * (acc[mi][ni][half * 2 + 0] + b0.x + b1.x);
                res.y = 0.5f * (acc[mi][ni][half * 2 + 1] + b0.y + b1.y);
                *reinterpret_cast<float2*>(out + o) = res;
            }
        }
    }
}

// ============================================================
extern "C" void kernel_launch(void* const* d_in, const int* in_sizes, int n_in,
                              void* d_out, int out_size) {
    const float* x    = (const float*)d_in[0];
    const float* adj  = (const float*)d_in[1];
    const float* Wmap = (const float*)d_in[2];
    const float* a1w  = (const float*)d_in[3];
    const float* a1b  = (const float*)d_in[4];
    const float* a2w  = (const float*)d_in[5];
    const float* a2b  = (const float*)d_in[6];
    const float* kern = (const float*)d_in[7];
    const float* bias = (const float*)d_in[8];
    float* out = (float*)d_out;

    prep_kernel<<<1, 256>>>(Wmap, a1w, a2w);
    score_kernel<<<1024, 256>>>(x, a1b, a2b);
    gat_main<<<N_NODES, 256>>>(adj, x);
    gemm_tf32<<<256, 128>>>(kern, bias, out);
}